// round 8
// baseline (speedup 1.0000x reference)
#include <cuda_runtime.h>
#include <math.h>

#define BB      8
#define LL      1000
#define FFE     7
#define DMODEL  512
#define NHEAD   8
#define DK      64
#define PDIM    16
#define DFFN    2048
#define NLAYER  4
#define NPRED   50
#define NTOK    (BB*LL)
#define LN_EPS  1e-5f
#define ATT_SCALE 0.125f

// ---------------- scratch (device globals: no cudaMalloc allowed) ----------------
__device__ float g_h  [NTOK*DMODEL];
__device__ float g_q  [NTOK*DMODEL];
__device__ float g_k  [NTOK*DMODEL];
__device__ float g_v  [NTOK*DMODEL];
__device__ float g_ctx[NTOK*DMODEL];
__device__ float g_t0 [NTOK*DMODEL];
__device__ float g_y  [NTOK*DMODEL];
__device__ float g_mid[NTOK*DFFN];
__device__ float g_qp [NTOK*NHEAD*PDIM];
__device__ float g_kp [NTOK*NHEAD*PDIM];

__device__ __forceinline__ float fast_tanh(float x){
    x = fminf(fmaxf(x, -15.0f), 15.0f);
    float t = __expf(2.0f*x);
    return __fdividef(t - 1.0f, t + 1.0f);
}

// ---------------- embedding: h = x@emb_w + emb_b + pe ----------------
__global__ void embed_kernel(const float* __restrict__ x, const float* __restrict__ ew,
                             const float* __restrict__ eb, const float* __restrict__ pe,
                             float* __restrict__ out)
{
    int idx = blockIdx.x*blockDim.x + threadIdx.x;
    if (idx >= NTOK*(DMODEL/4)) return;
    int d4  = idx & (DMODEL/4 - 1);
    int tok = idx >> 7;
    int lpos = tok % LL;
    int d = d4*4;
    float4 acc = *(const float4*)(eb + d);
    float4 pv  = *(const float4*)(pe + (size_t)lpos*DMODEL + d);
    acc.x += pv.x; acc.y += pv.y; acc.z += pv.z; acc.w += pv.w;
    #pragma unroll
    for (int f = 0; f < FFE; f++){
        float xv = x[tok*FFE + f];
        float4 wv = *(const float4*)(ew + (size_t)f*DMODEL + d);
        acc.x = fmaf(xv, wv.x, acc.x);
        acc.y = fmaf(xv, wv.y, acc.y);
        acc.z = fmaf(xv, wv.z, acc.z);
        acc.w = fmaf(xv, wv.w, acc.w);
    }
    *(float4*)(out + (size_t)tok*DMODEL + d) = acc;
}

// ---------------- generic tiled SGEMM: C = A[M,K]@W[K,N] + bias (+epilogue) ------
// EPI: 0 = bias, 1 = bias+relu, 2 = bias+residual(res)
template<int EPI>
__global__ __launch_bounds__(256, 2) void sgemm_kernel(
    const float* __restrict__ A, const float* __restrict__ W,
    const float* __restrict__ bias, const float* __restrict__ res,
    float* __restrict__ C, int M, int N, int K)
{
    __shared__ float As[16][132];   // transposed A tile [k][m], padded
    __shared__ float Bs[16][128];   // B tile [k][n]
    const int tid = threadIdx.x;
    const int tx = tid & 15, ty = tid >> 4;
    const int m0 = blockIdx.y * 128, n0 = blockIdx.x * 128;

    float acc[8][8];
    #pragma unroll
    for (int i = 0; i < 8; i++)
        #pragma unroll
        for (int j = 0; j < 8; j++) acc[i][j] = 0.f;

    const int ar = tid >> 1;           // A row in tile (0..127)
    const int ac = (tid & 1) * 8;      // A col offset within 16
    const int br = tid >> 4;           // B row in tile (0..15)
    const int bc = (tid & 15) * 8;     // B col offset
    const int gm_a = m0 + ar;
    const float* Abase = A + (size_t)gm_a * K + ac;
    const float* Bbase = W + (size_t)br * N + n0 + bc;

    for (int kt = 0; kt < K; kt += 16){
        float4 a0 = make_float4(0,0,0,0), a1 = a0;
        if (gm_a < M){
            a0 = *(const float4*)(Abase + kt);
            a1 = *(const float4*)(Abase + kt + 4);
        }
        float4 b0 = *(const float4*)(Bbase + (size_t)kt * N);
        float4 b1 = *(const float4*)(Bbase + (size_t)kt * N + 4);
        __syncthreads();
        As[ac+0][ar]=a0.x; As[ac+1][ar]=a0.y; As[ac+2][ar]=a0.z; As[ac+3][ar]=a0.w;
        As[ac+4][ar]=a1.x; As[ac+5][ar]=a1.y; As[ac+6][ar]=a1.z; As[ac+7][ar]=a1.w;
        *(float4*)&Bs[br][bc]   = b0;
        *(float4*)&Bs[br][bc+4] = b1;
        __syncthreads();
        #pragma unroll
        for (int k = 0; k < 16; k++){
            float4 xa0 = *(const float4*)&As[k][ty*8];
            float4 xa1 = *(const float4*)&As[k][ty*8+4];
            float4 xb0 = *(const float4*)&Bs[k][tx*8];
            float4 xb1 = *(const float4*)&Bs[k][tx*8+4];
            float av[8] = {xa0.x,xa0.y,xa0.z,xa0.w,xa1.x,xa1.y,xa1.z,xa1.w};
            float bw[8] = {xb0.x,xb0.y,xb0.z,xb0.w,xb1.x,xb1.y,xb1.z,xb1.w};
            #pragma unroll
            for (int i = 0; i < 8; i++)
                #pragma unroll
                for (int j = 0; j < 8; j++)
                    acc[i][j] = fmaf(av[i], bw[j], acc[i][j]);
        }
    }

    float bv[8];
    #pragma unroll
    for (int j = 0; j < 8; j++) bv[j] = bias[n0 + tx*8 + j];
    #pragma unroll
    for (int i = 0; i < 8; i++){
        int gm = m0 + ty*8 + i;
        if (gm >= M) continue;
        float* Crow = C + (size_t)gm * N + n0 + tx*8;
        float vals[8];
        #pragma unroll
        for (int j = 0; j < 8; j++){
            float vv = acc[i][j] + bv[j];
            if (EPI == 1) vv = fmaxf(vv, 0.f);
            vals[j] = vv;
        }
        if (EPI == 2){
            const float* Rrow = res + (size_t)gm * N + n0 + tx*8;
            float4 r0 = *(const float4*)Rrow;
            float4 r1 = *(const float4*)(Rrow + 4);
            vals[0]+=r0.x; vals[1]+=r0.y; vals[2]+=r0.z; vals[3]+=r0.w;
            vals[4]+=r1.x; vals[5]+=r1.y; vals[6]+=r1.z; vals[7]+=r1.w;
        }
        *(float4*)Crow     = make_float4(vals[0],vals[1],vals[2],vals[3]);
        *(float4*)(Crow+4) = make_float4(vals[4],vals[5],vals[6],vals[7]);
    }
}

// ---------------- learned-mask projection: out[tok,h,p] = q[tok,h,:]@Wm + bm ----
__global__ void lm_proj_kernel(const float* __restrict__ X, const float* __restrict__ Wm,
                               const float* __restrict__ bm, float* __restrict__ out)
{
    int t = blockIdx.x*blockDim.x + threadIdx.x;
    if (t >= NTOK*NHEAD*PDIM) return;
    int p   = t & (PDIM-1);
    int hh  = (t >> 4) & (NHEAD-1);
    int tok = t >> 7;
    const float* xr = X + (size_t)tok*DMODEL + hh*DK;
    float s = bm[p];
    #pragma unroll
    for (int d = 0; d < DK; d++) s = fmaf(xr[d], Wm[d*PDIM + p], s);
    out[t] = s;
}

// ---------------- flash attention with learned-mask bias --------------------------
// grid: (ceil(L/64), B*H), block 256, dynamic smem
#define FLASH_SMEM ((14336 + 64*65) * 4)

__global__ __launch_bounds__(256) void flash_kernel(
    const float* __restrict__ Q, const float* __restrict__ Kg, const float* __restrict__ Vg,
    const float* __restrict__ QP, const float* __restrict__ KP, float* __restrict__ O)
{
    extern __shared__ float smf[];
    float* Qt  = smf;            // [64][64] transposed: Qt[d*64 + r]
    float* QPt = smf + 4096;     // [16][64]
    float* Kt  = smf + 5120;     // [64][64] transposed
    float* KPt = smf + 9216;     // [16][64]
    float* Vs  = smf + 10240;    // [64][64] row-major [s][d]
    float* Ps  = smf + 14336;    // [64][65]

    const int tid = threadIdx.x;
    const int tx = tid & 15, ty = tid >> 4;
    const int q0 = blockIdx.x * 64;
    const int b  = blockIdx.y >> 3;
    const int h  = blockIdx.y & 7;

    // load Q tile (transposed) + QP tile (transposed)
    #pragma unroll
    for (int i = 0; i < 4; i++){
        int f = tid + 256*i;
        int r = f >> 4, c4 = f & 15;
        int lq = q0 + r;
        float4 v = make_float4(0,0,0,0);
        if (lq < LL) v = *(const float4*)(Q + ((size_t)(b*LL + lq)*NHEAD + h)*DK + c4*4);
        int d = c4*4;
        Qt[(d+0)*64+r]=v.x; Qt[(d+1)*64+r]=v.y; Qt[(d+2)*64+r]=v.z; Qt[(d+3)*64+r]=v.w;
    }
    {
        int r = tid >> 2, c4 = tid & 3;
        int lq = q0 + r;
        float4 v = make_float4(0,0,0,0);
        if (lq < LL) v = *(const float4*)(QP + ((size_t)(b*LL + lq)*NHEAD + h)*PDIM + c4*4);
        int p = c4*4;
        QPt[(p+0)*64+r]=v.x; QPt[(p+1)*64+r]=v.y; QPt[(p+2)*64+r]=v.z; QPt[(p+3)*64+r]=v.w;
    }

    float mrow[4], lrow[4], acc[4][4];
    #pragma unroll
    for (int i = 0; i < 4; i++){
        mrow[i] = -1e30f; lrow[i] = 0.f;
        #pragma unroll
        for (int j = 0; j < 4; j++) acc[i][j] = 0.f;
    }

    for (int s0 = 0; s0 < LL; s0 += 64){
        __syncthreads();   // previous P·V finished reading Vs/Ps
        // load K (transposed), V (row-major), KP (transposed)
        #pragma unroll
        for (int i = 0; i < 4; i++){
            int f = tid + 256*i;
            int r = f >> 4, c4 = f & 15;
            int ls = s0 + r;
            float4 kv = make_float4(0,0,0,0), vv = kv;
            if (ls < LL){
                size_t base = ((size_t)(b*LL + ls)*NHEAD + h)*DK + c4*4;
                kv = *(const float4*)(Kg + base);
                vv = *(const float4*)(Vg + base);
            }
            int d = c4*4;
            Kt[(d+0)*64+r]=kv.x; Kt[(d+1)*64+r]=kv.y; Kt[(d+2)*64+r]=kv.z; Kt[(d+3)*64+r]=kv.w;
            *(float4*)&Vs[r*64 + d] = vv;
        }
        {
            int r = tid >> 2, c4 = tid & 3;
            int ls = s0 + r;
            float4 v = make_float4(0,0,0,0);
            if (ls < LL) v = *(const float4*)(KP + ((size_t)(b*LL + ls)*NHEAD + h)*PDIM + c4*4);
            int p = c4*4;
            KPt[(p+0)*64+r]=v.x; KPt[(p+1)*64+r]=v.y; KPt[(p+2)*64+r]=v.z; KPt[(p+3)*64+r]=v.w;
        }
        __syncthreads();

        float sv[4][4], slm[4][4];
        #pragma unroll
        for (int i = 0; i < 4; i++)
            #pragma unroll
            for (int j = 0; j < 4; j++){ sv[i][j]=0.f; slm[i][j]=0.f; }

        #pragma unroll 16
        for (int kk = 0; kk < DK; kk++){
            float4 qa = *(const float4*)&Qt[kk*64 + ty*4];
            float4 kb = *(const float4*)&Kt[kk*64 + tx*4];
            float av[4] = {qa.x,qa.y,qa.z,qa.w};
            float bw[4] = {kb.x,kb.y,kb.z,kb.w};
            #pragma unroll
            for (int i = 0; i < 4; i++)
                #pragma unroll
                for (int j = 0; j < 4; j++)
                    sv[i][j] = fmaf(av[i], bw[j], sv[i][j]);
        }
        #pragma unroll
        for (int kk = 0; kk < PDIM; kk++){
            float4 qa = *(const float4*)&QPt[kk*64 + ty*4];
            float4 kb = *(const float4*)&KPt[kk*64 + tx*4];
            float av[4] = {qa.x,qa.y,qa.z,qa.w};
            float bw[4] = {kb.x,kb.y,kb.z,kb.w};
            #pragma unroll
            for (int i = 0; i < 4; i++)
                #pragma unroll
                for (int j = 0; j < 4; j++)
                    slm[i][j] = fmaf(av[i], bw[j], slm[i][j]);
        }
        #pragma unroll
        for (int i = 0; i < 4; i++)
            #pragma unroll
            for (int j = 0; j < 4; j++){
                float val = sv[i][j]*ATT_SCALE + fast_tanh(slm[i][j]);
                if (s0 + tx*4 + j >= LL) val = -1e30f;
                sv[i][j] = val;
            }

        // online softmax (row = 16-lane shuffle group)
        #pragma unroll
        for (int i = 0; i < 4; i++){
            float rmax = fmaxf(fmaxf(sv[i][0],sv[i][1]), fmaxf(sv[i][2],sv[i][3]));
            #pragma unroll
            for (int off = 8; off > 0; off >>= 1)
                rmax = fmaxf(rmax, __shfl_xor_sync(0xffffffffu, rmax, off, 16));
            float mnew  = fmaxf(mrow[i], rmax);
            float alpha = __expf(mrow[i] - mnew);
            float pv[4]; float rs = 0.f;
            #pragma unroll
            for (int j = 0; j < 4; j++){ pv[j] = __expf(sv[i][j] - mnew); rs += pv[j]; }
            #pragma unroll
            for (int off = 8; off > 0; off >>= 1)
                rs += __shfl_xor_sync(0xffffffffu, rs, off, 16);
            lrow[i] = lrow[i]*alpha + rs;
            mrow[i] = mnew;
            #pragma unroll
            for (int j = 0; j < 4; j++){
                acc[i][j] *= alpha;
                Ps[(ty*4+i)*65 + tx*4 + j] = pv[j];
            }
        }
        __syncwarp();   // Ps rows are produced/consumed within one warp's 16-lane group

        // O += P @ V
        #pragma unroll 8
        for (int ss = 0; ss < 64; ss++){
            float4 vv = *(const float4*)&Vs[ss*64 + tx*4];
            #pragma unroll
            for (int i = 0; i < 4; i++){
                float pa = Ps[(ty*4+i)*65 + ss];
                acc[i][0] = fmaf(pa, vv.x, acc[i][0]);
                acc[i][1] = fmaf(pa, vv.y, acc[i][1]);
                acc[i][2] = fmaf(pa, vv.z, acc[i][2]);
                acc[i][3] = fmaf(pa, vv.w, acc[i][3]);
            }
        }
    }

    #pragma unroll
    for (int i = 0; i < 4; i++){
        int lq = q0 + ty*4 + i;
        if (lq >= LL) continue;
        float inv = __fdividef(1.f, lrow[i]);
        float4 o = make_float4(acc[i][0]*inv, acc[i][1]*inv, acc[i][2]*inv, acc[i][3]*inv);
        *(float4*)(O + ((size_t)(b*LL + lq)*NHEAD + h)*DK + tx*4) = o;
    }
}

// ---------------- layernorm: out = LN(A [+ Add]) * g + b ------------------------
__global__ void ln_kernel(const float* __restrict__ A, const float* __restrict__ Add,
                          const float* __restrict__ g, const float* __restrict__ bb,
                          float* __restrict__ out)
{
    int row = blockIdx.x;
    int tid = threadIdx.x;   // 128
    size_t off = (size_t)row*DMODEL + tid*4;
    float4 v = *(const float4*)(A + off);
    if (Add){
        float4 w = *(const float4*)(Add + off);
        v.x+=w.x; v.y+=w.y; v.z+=w.z; v.w+=w.w;
    }
    float s  = v.x+v.y+v.z+v.w;
    float s2 = v.x*v.x + v.y*v.y + v.z*v.z + v.w*v.w;
    #pragma unroll
    for (int o = 16; o > 0; o >>= 1){
        s  += __shfl_down_sync(0xffffffffu, s,  o);
        s2 += __shfl_down_sync(0xffffffffu, s2, o);
    }
    __shared__ float red[8];
    int wid = tid >> 5;
    if ((tid & 31) == 0){ red[wid] = s; red[wid+4] = s2; }
    __syncthreads();
    if (tid == 0){
        float ts  = red[0]+red[1]+red[2]+red[3];
        float ts2 = red[4]+red[5]+red[6]+red[7];
        float mean = ts * (1.f/DMODEL);
        float var  = ts2 * (1.f/DMODEL) - mean*mean;
        red[0] = mean; red[1] = rsqrtf(var + LN_EPS);
    }
    __syncthreads();
    float mean = red[0], rstd = red[1];
    float4 gv = *(const float4*)(g  + tid*4);
    float4 bv = *(const float4*)(bb + tid*4);
    float4 o;
    o.x = (v.x-mean)*rstd*gv.x + bv.x;
    o.y = (v.y-mean)*rstd*gv.y + bv.y;
    o.z = (v.z-mean)*rstd*gv.z + bv.z;
    o.w = (v.w-mean)*rstd*gv.w + bv.w;
    *(float4*)(out + off) = o;
}

// ---------------- final: LN(h[b, L-1, :]) @ fc_w + fc_b --------------------------
__global__ void final_kernel(const float* __restrict__ Hbuf, const float* __restrict__ gn,
    const float* __restrict__ bn, const float* __restrict__ fw, const float* __restrict__ fb,
    float* __restrict__ out)
{
    __shared__ float sh[DMODEL];
    __shared__ float red[34];
    int b = blockIdx.x, tid = threadIdx.x;  // 512
    float v = Hbuf[((size_t)(b*LL + LL-1))*DMODEL + tid];
    float s = v, s2 = v*v;
    #pragma unroll
    for (int o = 16; o > 0; o >>= 1){
        s  += __shfl_down_sync(0xffffffffu, s,  o);
        s2 += __shfl_down_sync(0xffffffffu, s2, o);
    }
    int wid = tid >> 5;
    if ((tid & 31) == 0){ red[wid] = s; red[wid+17] = s2; }
    __syncthreads();
    if (tid == 0){
        float ts = 0.f, ts2 = 0.f;
        #pragma unroll
        for (int i = 0; i < 16; i++){ ts += red[i]; ts2 += red[i+17]; }
        float mean = ts * (1.f/DMODEL);
        float var  = ts2 * (1.f/DMODEL) - mean*mean;
        red[16] = mean; red[33] = rsqrtf(var + LN_EPS);
    }
    __syncthreads();
    float mean = red[16], rstd = red[33];
    sh[tid] = (v - mean)*rstd*gn[tid] + bn[tid];
    __syncthreads();
    if (tid < NPRED){
        float acc = fb[tid];
        #pragma unroll 8
        for (int d = 0; d < DMODEL; d++) acc = fmaf(sh[d], fw[d*NPRED + tid], acc);
        out[b*NPRED + tid] = acc;
    }
}

// ---------------- host orchestration ---------------------------------------------
extern "C" void kernel_launch(void* const* d_in, const int* in_sizes, int n_in,
                              void* d_out, int out_size)
{
    const float* x     = (const float*)d_in[0];
    const float* emb_w = (const float*)d_in[1];
    const float* emb_b = (const float*)d_in[2];
    const float* pe    = (const float*)d_in[3];
    const float* Wq    = (const float*)d_in[4];
    const float* bq    = (const float*)d_in[5];
    const float* Wk    = (const float*)d_in[6];
    const float* bk    = (const float*)d_in[7];
    const float* Wv    = (const float*)d_in[8];
    const float* bvv   = (const float*)d_in[9];
    const float* Wo    = (const float*)d_in[10];
    const float* bo    = (const float*)d_in[11];
    const float* W1    = (const float*)d_in[12];
    const float* b1    = (const float*)d_in[13];
    const float* W2    = (const float*)d_in[14];
    const float* b2    = (const float*)d_in[15];
    const float* g1    = (const float*)d_in[16];
    const float* be1   = (const float*)d_in[17];
    const float* g2    = (const float*)d_in[18];
    const float* be2   = (const float*)d_in[19];
    const float* lm_qw = (const float*)d_in[20];
    const float* lm_qb = (const float*)d_in[21];
    const float* lm_kw = (const float*)d_in[22];
    const float* lm_kb = (const float*)d_in[23];
    const float* gn    = (const float*)d_in[24];
    const float* bn    = (const float*)d_in[25];
    const float* fc_w  = (const float*)d_in[26];
    const float* fc_b  = (const float*)d_in[27];

    float *h,*q,*k,*v,*ctx,*t0,*y,*mid,*qp,*kp;
    cudaGetSymbolAddress((void**)&h,   g_h);
    cudaGetSymbolAddress((void**)&q,   g_q);
    cudaGetSymbolAddress((void**)&k,   g_k);
    cudaGetSymbolAddress((void**)&v,   g_v);
    cudaGetSymbolAddress((void**)&ctx, g_ctx);
    cudaGetSymbolAddress((void**)&t0,  g_t0);
    cudaGetSymbolAddress((void**)&y,   g_y);
    cudaGetSymbolAddress((void**)&mid, g_mid);
    cudaGetSymbolAddress((void**)&qp,  g_qp);
    cudaGetSymbolAddress((void**)&kp,  g_kp);

    cudaFuncSetAttribute(flash_kernel, cudaFuncAttributeMaxDynamicSharedMemorySize, FLASH_SMEM);

    embed_kernel<<<(NTOK*(DMODEL/4)+255)/256, 256>>>(x, emb_w, emb_b, pe, h);

    dim3 g512 (DMODEL/128, (NTOK+127)/128);   // (4, 63)
    dim3 g2048(DFFN/128,   (NTOK+127)/128);   // (16, 63)
    int lmN = NTOK*NHEAD*PDIM;

    for (int i = 0; i < NLAYER; i++){
        const float* Wqi = Wq + (size_t)i*DMODEL*DMODEL;  const float* bqi = bq + (size_t)i*DMODEL;
        const float* Wki = Wk + (size_t)i*DMODEL*DMODEL;  const float* bki = bk + (size_t)i*DMODEL;
        const float* Wvi = Wv + (size_t)i*DMODEL*DMODEL;  const float* bvi = bvv + (size_t)i*DMODEL;
        const float* Woi = Wo + (size_t)i*DMODEL*DMODEL;  const float* boi = bo + (size_t)i*DMODEL;
        const float* W1i = W1 + (size_t)i*DMODEL*DFFN;    const float* b1i = b1 + (size_t)i*DFFN;
        const float* W2i = W2 + (size_t)i*DFFN*DMODEL;    const float* b2i = b2 + (size_t)i*DMODEL;
        const float* g1i = g1 + (size_t)i*DMODEL;  const float* be1i = be1 + (size_t)i*DMODEL;
        const float* g2i = g2 + (size_t)i*DMODEL;  const float* be2i = be2 + (size_t)i*DMODEL;

        sgemm_kernel<0><<<g512, 256>>>(h, Wqi, bqi, nullptr, q, NTOK, DMODEL, DMODEL);
        sgemm_kernel<0><<<g512, 256>>>(h, Wki, bki, nullptr, k, NTOK, DMODEL, DMODEL);
        sgemm_kernel<0><<<g512, 256>>>(h, Wvi, bvi, nullptr, v, NTOK, DMODEL, DMODEL);

        lm_proj_kernel<<<(lmN+255)/256, 256>>>(q, lm_qw, lm_qb, qp);
        lm_proj_kernel<<<(lmN+255)/256, 256>>>(k, lm_kw, lm_kb, kp);

        flash_kernel<<<dim3((LL+63)/64, BB*NHEAD), 256, FLASH_SMEM>>>(q, k, v, qp, kp, ctx);

        sgemm_kernel<2><<<g512, 256>>>(ctx, Woi, boi, h, t0, NTOK, DMODEL, DMODEL); // t0 = h + ctx@Wo+bo
        ln_kernel<<<NTOK, 128>>>(t0, nullptr, g1i, be1i, h);                        // h = LN(t0)

        sgemm_kernel<1><<<g2048, 256>>>(h,   W1i, b1i, nullptr, mid, NTOK, DFFN,   DMODEL); // relu
        sgemm_kernel<0><<<g512,  256>>>(mid, W2i, b2i, nullptr, y,   NTOK, DMODEL, DFFN);

        ln_kernel<<<NTOK, 128>>>(h,  y, g2i, be2i, t0);   // h2 = LN(h + y)
        ln_kernel<<<NTOK, 128>>>(t0, y, g2i, be2i, h);    // h  = LN(h2 + y)   (module applies norm2 twice)
    }

    final_kernel<<<BB, DMODEL>>>(h, gn, bn, fc_w, fc_b, (float*)d_out);
}

// round 12
// speedup vs baseline: 1.0838x; 1.0838x over previous
#include <cuda_runtime.h>
#include <math.h>

#define BB      8
#define LL      1000
#define FFE     7
#define DMODEL  512
#define NHEAD   8
#define DK      64
#define PDIM    16
#define DFFN    2048
#define NLAYER  4
#define NPRED   50
#define NTOK    (BB*LL)
#define LN_EPS  1e-5f
#define ATT_SCALE 0.125f

// ---------------- scratch (device globals: no cudaMalloc allowed) ----------------
__device__ float g_h  [NTOK*DMODEL];
__device__ float g_q  [NTOK*DMODEL];
__device__ float g_k  [NTOK*DMODEL];
__device__ float g_v  [NTOK*DMODEL];
__device__ float g_ctx[NTOK*DMODEL];
__device__ float g_t0 [NTOK*DMODEL];
__device__ float g_y  [NTOK*DMODEL];
__device__ float g_mid[NTOK*DFFN];
__device__ float g_qp [NTOK*NHEAD*PDIM];
__device__ float g_kp [NTOK*NHEAD*PDIM];

__device__ __forceinline__ float fast_tanh(float x){
    x = fminf(fmaxf(x, -15.0f), 15.0f);
    float t = __expf(2.0f*x);
    return __fdividef(t - 1.0f, t + 1.0f);
}

__device__ __forceinline__ unsigned f2tf(float x){
    unsigned r;
    asm("cvt.rna.tf32.f32 %0, %1;" : "=r"(r) : "f"(x));
    return r;
}

__device__ __forceinline__ void mma_tf32(float* c, const unsigned* a, const unsigned* b){
    asm volatile("mma.sync.aligned.m16n8k8.row.col.f32.tf32.tf32.f32 "
        "{%0,%1,%2,%3}, {%4,%5,%6,%7}, {%8,%9}, {%0,%1,%2,%3};"
        : "+f"(c[0]), "+f"(c[1]), "+f"(c[2]), "+f"(c[3])
        : "r"(a[0]), "r"(a[1]), "r"(a[2]), "r"(a[3]), "r"(b[0]), "r"(b[1]));
}

// ---------------- embedding: h = x@emb_w + emb_b + pe ----------------
__global__ void embed_kernel(const float* __restrict__ x, const float* __restrict__ ew,
                             const float* __restrict__ eb, const float* __restrict__ pe,
                             float* __restrict__ out)
{
    int idx = blockIdx.x*blockDim.x + threadIdx.x;
    if (idx >= NTOK*(DMODEL/4)) return;
    int d4  = idx & (DMODEL/4 - 1);
    int tok = idx >> 7;
    int lpos = tok % LL;
    int d = d4*4;
    float4 acc = *(const float4*)(eb + d);
    float4 pv  = *(const float4*)(pe + (size_t)lpos*DMODEL + d);
    acc.x += pv.x; acc.y += pv.y; acc.z += pv.z; acc.w += pv.w;
    #pragma unroll
    for (int f = 0; f < FFE; f++){
        float xv = x[tok*FFE + f];
        float4 wv = *(const float4*)(ew + (size_t)f*DMODEL + d);
        acc.x = fmaf(xv, wv.x, acc.x);
        acc.y = fmaf(xv, wv.y, acc.y);
        acc.z = fmaf(xv, wv.z, acc.z);
        acc.w = fmaf(xv, wv.w, acc.w);
    }
    *(float4*)(out + (size_t)tok*DMODEL + d) = acc;
}

// ---------------- TF32 tensor-core GEMM: C = A[M,K]@W[K,N] + bias (+epilogue) ----
// EPI: 0 = bias, 1 = bias+relu, 2 = bias+residual(res)
// Block: 128 threads (4 warps), tile 128x128, k-tile 32. Warp tile 64x64.
#define AS_STRIDE 36     // 32 + 4 pad: frag LDS banks = gid*4+tig -> conflict-free
#define BS_STRIDE 136    // 128 + 8 pad: frag LDS banks = tig*8+gid -> conflict-free

template<int EPI>
__global__ __launch_bounds__(128, 2) void mma_gemm_kernel(
    const float* __restrict__ A, const float* __restrict__ W,
    const float* __restrict__ bias, const float* __restrict__ res,
    float* __restrict__ C, int M, int N, int K)
{
    __shared__ unsigned As[128*AS_STRIDE];   // [m][k]
    __shared__ unsigned Bs[32*BS_STRIDE];    // [k][n]
    const int tid  = threadIdx.x;
    const int wid  = tid >> 5, lane = tid & 31;
    const int wm   = (wid & 1) * 64;         // warp row offset in tile
    const int wn   = (wid >> 1) * 64;        // warp col offset in tile
    const int m0   = blockIdx.y * 128, n0 = blockIdx.x * 128;
    const int gid  = lane >> 2, tig = lane & 3;

    float acc[4][8][4];
    #pragma unroll
    for (int mt = 0; mt < 4; mt++)
        #pragma unroll
        for (int nt = 0; nt < 8; nt++)
            #pragma unroll
            for (int j = 0; j < 4; j++) acc[mt][nt][j] = 0.f;

    for (int k0 = 0; k0 < K; k0 += 32){
        // ---- stage A tile [128][32] : 1024 float4 over 128 threads = 8 iters
        #pragma unroll
        for (int it = 0; it < 8; it++){
            int i  = it*128 + tid;
            int r  = i >> 3, c4 = (i & 7) * 4;
            float4 v = make_float4(0,0,0,0);
            int gm = m0 + r;
            if (gm < M) v = *(const float4*)(A + (size_t)gm*K + k0 + c4);
            *(uint4*)&As[r*AS_STRIDE + c4] =
                make_uint4(f2tf(v.x), f2tf(v.y), f2tf(v.z), f2tf(v.w));
        }
        // ---- stage B tile [32][128]
        #pragma unroll
        for (int it = 0; it < 8; it++){
            int i  = it*128 + tid;
            int kr = i >> 5, c4 = (i & 31) * 4;
            float4 v = *(const float4*)(W + (size_t)(k0+kr)*N + n0 + c4);
            *(uint4*)&Bs[kr*BS_STRIDE + c4] =
                make_uint4(f2tf(v.x), f2tf(v.y), f2tf(v.z), f2tf(v.w));
        }
        __syncthreads();

        #pragma unroll
        for (int k8 = 0; k8 < 4; k8++){
            unsigned afr[4][4], bfr[8][2];
            #pragma unroll
            for (int mt = 0; mt < 4; mt++){
                int r = wm + mt*16 + gid;
                const unsigned* p0 = &As[r*AS_STRIDE + k8*8];
                const unsigned* p1 = &As[(r+8)*AS_STRIDE + k8*8];
                afr[mt][0] = p0[tig];
                afr[mt][1] = p1[tig];
                afr[mt][2] = p0[tig+4];
                afr[mt][3] = p1[tig+4];
            }
            #pragma unroll
            for (int nt = 0; nt < 8; nt++){
                int n = wn + nt*8 + gid;
                bfr[nt][0] = Bs[(k8*8 + tig  )*BS_STRIDE + n];
                bfr[nt][1] = Bs[(k8*8 + tig+4)*BS_STRIDE + n];
            }
            #pragma unroll
            for (int mt = 0; mt < 4; mt++)
                #pragma unroll
                for (int nt = 0; nt < 8; nt++)
                    mma_tf32(acc[mt][nt], afr[mt], bfr[nt]);
        }
        __syncthreads();
    }

    // ---- epilogue: C[gid][2*tig], rows gid / gid+8 per 16x8 fragment
    #pragma unroll
    for (int mt = 0; mt < 4; mt++){
        #pragma unroll
        for (int half = 0; half < 2; half++){
            int gm = m0 + wm + mt*16 + gid + half*8;
            if (gm >= M) continue;
            float* crow = C + (size_t)gm*N;
            const float* rrow = (EPI == 2) ? (res + (size_t)gm*N) : nullptr;
            #pragma unroll
            for (int nt = 0; nt < 8; nt++){
                int gn = n0 + wn + nt*8 + tig*2;
                float v0 = acc[mt][nt][half*2+0] + bias[gn];
                float v1 = acc[mt][nt][half*2+1] + bias[gn+1];
                if (EPI == 1){ v0 = fmaxf(v0, 0.f); v1 = fmaxf(v1, 0.f); }
                if (EPI == 2){ v0 += rrow[gn]; v1 += rrow[gn+1]; }
                *(float2*)(crow + gn) = make_float2(v0, v1);
            }
        }
    }
}

// ---------------- learned-mask projection: out[tok,h,p] = q[tok,h,:]@Wm + bm ----
__global__ void lm_proj_kernel(const float* __restrict__ X, const float* __restrict__ Wm,
                               const float* __restrict__ bm, float* __restrict__ out)
{
    int t = blockIdx.x*blockDim.x + threadIdx.x;
    if (t >= NTOK*NHEAD*PDIM) return;
    int p   = t & (PDIM-1);
    int hh  = (t >> 4) & (NHEAD-1);
    int tok = t >> 7;
    const float* xr = X + (size_t)tok*DMODEL + hh*DK;
    float s = bm[p];
    #pragma unroll
    for (int d = 0; d < DK; d++) s = fmaf(xr[d], Wm[d*PDIM + p], s);
    out[t] = s;
}

// ---------------- flash attention with learned-mask bias --------------------------
// grid: (ceil(L/64), B*H), block 256, dynamic smem
#define FLASH_SMEM ((14336 + 64*65) * 4)

__global__ __launch_bounds__(256) void flash_kernel(
    const float* __restrict__ Q, const float* __restrict__ Kg, const float* __restrict__ Vg,
    const float* __restrict__ QP, const float* __restrict__ KP, float* __restrict__ O)
{
    extern __shared__ float smf[];
    float* Qt  = smf;            // [64][64] transposed: Qt[d*64 + r]
    float* QPt = smf + 4096;     // [16][64]
    float* Kt  = smf + 5120;     // [64][64] transposed
    float* KPt = smf + 9216;     // [16][64]
    float* Vs  = smf + 10240;    // [64][64] row-major [s][d]
    float* Ps  = smf + 14336;    // [64][65]

    const int tid = threadIdx.x;
    const int tx = tid & 15, ty = tid >> 4;
    const int q0 = blockIdx.x * 64;
    const int b  = blockIdx.y >> 3;
    const int h  = blockIdx.y & 7;

    #pragma unroll
    for (int i = 0; i < 4; i++){
        int f = tid + 256*i;
        int r = f >> 4, c4 = f & 15;
        int lq = q0 + r;
        float4 v = make_float4(0,0,0,0);
        if (lq < LL) v = *(const float4*)(Q + ((size_t)(b*LL + lq)*NHEAD + h)*DK + c4*4);
        int d = c4*4;
        Qt[(d+0)*64+r]=v.x; Qt[(d+1)*64+r]=v.y; Qt[(d+2)*64+r]=v.z; Qt[(d+3)*64+r]=v.w;
    }
    {
        int r = tid >> 2, c4 = tid & 3;
        int lq = q0 + r;
        float4 v = make_float4(0,0,0,0);
        if (lq < LL) v = *(const float4*)(QP + ((size_t)(b*LL + lq)*NHEAD + h)*PDIM + c4*4);
        int p = c4*4;
        QPt[(p+0)*64+r]=v.x; QPt[(p+1)*64+r]=v.y; QPt[(p+2)*64+r]=v.z; QPt[(p+3)*64+r]=v.w;
    }

    float mrow[4], lrow[4], acc[4][4];
    #pragma unroll
    for (int i = 0; i < 4; i++){
        mrow[i] = -1e30f; lrow[i] = 0.f;
        #pragma unroll
        for (int j = 0; j < 4; j++) acc[i][j] = 0.f;
    }

    for (int s0 = 0; s0 < LL; s0 += 64){
        __syncthreads();
        #pragma unroll
        for (int i = 0; i < 4; i++){
            int f = tid + 256*i;
            int r = f >> 4, c4 = f & 15;
            int ls = s0 + r;
            float4 kv = make_float4(0,0,0,0), vv = kv;
            if (ls < LL){
                size_t base = ((size_t)(b*LL + ls)*NHEAD + h)*DK + c4*4;
                kv = *(const float4*)(Kg + base);
                vv = *(const float4*)(Vg + base);
            }
            int d = c4*4;
            Kt[(d+0)*64+r]=kv.x; Kt[(d+1)*64+r]=kv.y; Kt[(d+2)*64+r]=kv.z; Kt[(d+3)*64+r]=kv.w;
            *(float4*)&Vs[r*64 + d] = vv;
        }
        {
            int r = tid >> 2, c4 = tid & 3;
            int ls = s0 + r;
            float4 v = make_float4(0,0,0,0);
            if (ls < LL) v = *(const float4*)(KP + ((size_t)(b*LL + ls)*NHEAD + h)*PDIM + c4*4);
            int p = c4*4;
            KPt[(p+0)*64+r]=v.x; KPt[(p+1)*64+r]=v.y; KPt[(p+2)*64+r]=v.z; KPt[(p+3)*64+r]=v.w;
        }
        __syncthreads();

        float sv[4][4], slm[4][4];
        #pragma unroll
        for (int i = 0; i < 4; i++)
            #pragma unroll
            for (int j = 0; j < 4; j++){ sv[i][j]=0.f; slm[i][j]=0.f; }

        #pragma unroll 16
        for (int kk = 0; kk < DK; kk++){
            float4 qa = *(const float4*)&Qt[kk*64 + ty*4];
            float4 kb = *(const float4*)&Kt[kk*64 + tx*4];
            float av[4] = {qa.x,qa.y,qa.z,qa.w};
            float bw[4] = {kb.x,kb.y,kb.z,kb.w};
            #pragma unroll
            for (int i = 0; i < 4; i++)
                #pragma unroll
                for (int j = 0; j < 4; j++)
                    sv[i][j] = fmaf(av[i], bw[j], sv[i][j]);
        }
        #pragma unroll
        for (int kk = 0; kk < PDIM; kk++){
            float4 qa = *(const float4*)&QPt[kk*64 + ty*4];
            float4 kb = *(const float4*)&KPt[kk*64 + tx*4];
            float av[4] = {qa.x,qa.y,qa.z,qa.w};
            float bw[4] = {kb.x,kb.y,kb.z,kb.w};
            #pragma unroll
            for (int i = 0; i < 4; i++)
                #pragma unroll
                for (int j = 0; j < 4; j++)
                    slm[i][j] = fmaf(av[i], bw[j], slm[i][j]);
        }
        #pragma unroll
        for (int i = 0; i < 4; i++)
            #pragma unroll
            for (int j = 0; j < 4; j++){
                float val = sv[i][j]*ATT_SCALE + fast_tanh(slm[i][j]);
                if (s0 + tx*4 + j >= LL) val = -1e30f;
                sv[i][j] = val;
            }

        #pragma unroll
        for (int i = 0; i < 4; i++){
            float rmax = fmaxf(fmaxf(sv[i][0],sv[i][1]), fmaxf(sv[i][2],sv[i][3]));
            #pragma unroll
            for (int off = 8; off > 0; off >>= 1)
                rmax = fmaxf(rmax, __shfl_xor_sync(0xffffffffu, rmax, off, 16));
            float mnew  = fmaxf(mrow[i], rmax);
            float alpha = __expf(mrow[i] - mnew);
            float pv[4]; float rs = 0.f;
            #pragma unroll
            for (int j = 0; j < 4; j++){ pv[j] = __expf(sv[i][j] - mnew); rs += pv[j]; }
            #pragma unroll
            for (int off = 8; off > 0; off >>= 1)
                rs += __shfl_xor_sync(0xffffffffu, rs, off, 16);
            lrow[i] = lrow[i]*alpha + rs;
            mrow[i] = mnew;
            #pragma unroll
            for (int j = 0; j < 4; j++){
                acc[i][j] *= alpha;
                Ps[(ty*4+i)*65 + tx*4 + j] = pv[j];
            }
        }
        __syncwarp();

        #pragma unroll 8
        for (int ss = 0; ss < 64; ss++){
            float4 vv = *(const float4*)&Vs[ss*64 + tx*4];
            #pragma unroll
            for (int i = 0; i < 4; i++){
                float pa = Ps[(ty*4+i)*65 + ss];
                acc[i][0] = fmaf(pa, vv.x, acc[i][0]);
                acc[i][1] = fmaf(pa, vv.y, acc[i][1]);
                acc[i][2] = fmaf(pa, vv.z, acc[i][2]);
                acc[i][3] = fmaf(pa, vv.w, acc[i][3]);
            }
        }
    }

    #pragma unroll
    for (int i = 0; i < 4; i++){
        int lq = q0 + ty*4 + i;
        if (lq >= LL) continue;
        float inv = __fdividef(1.f, lrow[i]);
        float4 o = make_float4(acc[i][0]*inv, acc[i][1]*inv, acc[i][2]*inv, acc[i][3]*inv);
        *(float4*)(O + ((size_t)(b*LL + lq)*NHEAD + h)*DK + tx*4) = o;
    }
}

// ---------------- layernorm: out = LN(A [+ Add]) * g + b ------------------------
__global__ void ln_kernel(const float* __restrict__ A, const float* __restrict__ Add,
                          const float* __restrict__ g, const float* __restrict__ bb,
                          float* __restrict__ out)
{
    int row = blockIdx.x;
    int tid = threadIdx.x;   // 128
    size_t off = (size_t)row*DMODEL + tid*4;
    float4 v = *(const float4*)(A + off);
    if (Add){
        float4 w = *(const float4*)(Add + off);
        v.x+=w.x; v.y+=w.y; v.z+=w.z; v.w+=w.w;
    }
    float s  = v.x+v.y+v.z+v.w;
    float s2 = v.x*v.x + v.y*v.y + v.z*v.z + v.w*v.w;
    #pragma unroll
    for (int o = 16; o > 0; o >>= 1){
        s  += __shfl_down_sync(0xffffffffu, s,  o);
        s2 += __shfl_down_sync(0xffffffffu, s2, o);
    }
    __shared__ float red[8];
    int wid = tid >> 5;
    if ((tid & 31) == 0){ red[wid] = s; red[wid+4] = s2; }
    __syncthreads();
    if (tid == 0){
        float ts  = red[0]+red[1]+red[2]+red[3];
        float ts2 = red[4]+red[5]+red[6]+red[7];
        float mean = ts * (1.f/DMODEL);
        float var  = ts2 * (1.f/DMODEL) - mean*mean;
        red[0] = mean; red[1] = rsqrtf(var + LN_EPS);
    }
    __syncthreads();
    float mean = red[0], rstd = red[1];
    float4 gv = *(const float4*)(g  + tid*4);
    float4 bv = *(const float4*)(bb + tid*4);
    float4 o;
    o.x = (v.x-mean)*rstd*gv.x + bv.x;
    o.y = (v.y-mean)*rstd*gv.y + bv.y;
    o.z = (v.z-mean)*rstd*gv.z + bv.z;
    o.w = (v.w-mean)*rstd*gv.w + bv.w;
    *(float4*)(out + off) = o;
}

// ---------------- final: LN(h[b, L-1, :]) @ fc_w + fc_b --------------------------
__global__ void final_kernel(const float* __restrict__ Hbuf, const float* __restrict__ gn,
    const float* __restrict__ bn, const float* __restrict__ fw, const float* __restrict__ fb,
    float* __restrict__ out)
{
    __shared__ float sh[DMODEL];
    __shared__ float red[34];
    int b = blockIdx.x, tid = threadIdx.x;  // 512
    float v = Hbuf[((size_t)(b*LL + LL-1))*DMODEL + tid];
    float s = v, s2 = v*v;
    #pragma unroll
    for (int o = 16; o > 0; o >>= 1){
        s  += __shfl_down_sync(0xffffffffu, s,  o);
        s2 += __shfl_down_sync(0xffffffffu, s2, o);
    }
    int wid = tid >> 5;
    if ((tid & 31) == 0){ red[wid] = s; red[wid+17] = s2; }
    __syncthreads();
    if (tid == 0){
        float ts = 0.f, ts2 = 0.f;
        #pragma unroll
        for (int i = 0; i < 16; i++){ ts += red[i]; ts2 += red[i+17]; }
        float mean = ts * (1.f/DMODEL);
        float var  = ts2 * (1.f/DMODEL) - mean*mean;
        red[16] = mean; red[33] = rsqrtf(var + LN_EPS);
    }
    __syncthreads();
    float mean = red[16], rstd = red[33];
    sh[tid] = (v - mean)*rstd*gn[tid] + bn[tid];
    __syncthreads();
    if (tid < NPRED){
        float acc = fb[tid];
        #pragma unroll 8
        for (int d = 0; d < DMODEL; d++) acc = fmaf(sh[d], fw[d*NPRED + tid], acc);
        out[b*NPRED + tid] = acc;
    }
}

// ---------------- host orchestration ---------------------------------------------
extern "C" void kernel_launch(void* const* d_in, const int* in_sizes, int n_in,
                              void* d_out, int out_size)
{
    const float* x     = (const float*)d_in[0];
    const float* emb_w = (const float*)d_in[1];
    const float* emb_b = (const float*)d_in[2];
    const float* pe    = (const float*)d_in[3];
    const float* Wq    = (const float*)d_in[4];
    const float* bq    = (const float*)d_in[5];
    const float* Wk    = (const float*)d_in[6];
    const float* bk    = (const float*)d_in[7];
    const float* Wv    = (const float*)d_in[8];
    const float* bvv   = (const float*)d_in[9];
    const float* Wo    = (const float*)d_in[10];
    const float* bo    = (const float*)d_in[11];
    const float* W1    = (const float*)d_in[12];
    const float* b1    = (const float*)d_in[13];
    const float* W2    = (const float*)d_in[14];
    const float* b2    = (const float*)d_in[15];
    const float* g1    = (const float*)d_in[16];
    const float* be1   = (const float*)d_in[17];
    const float* g2    = (const float*)d_in[18];
    const float* be2   = (const float*)d_in[19];
    const float* lm_qw = (const float*)d_in[20];
    const float* lm_qb = (const float*)d_in[21];
    const float* lm_kw = (const float*)d_in[22];
    const float* lm_kb = (const float*)d_in[23];
    const float* gn    = (const float*)d_in[24];
    const float* bn    = (const float*)d_in[25];
    const float* fc_w  = (const float*)d_in[26];
    const float* fc_b  = (const float*)d_in[27];

    float *h,*q,*k,*v,*ctx,*t0,*y,*mid,*qp,*kp;
    cudaGetSymbolAddress((void**)&h,   g_h);
    cudaGetSymbolAddress((void**)&q,   g_q);
    cudaGetSymbolAddress((void**)&k,   g_k);
    cudaGetSymbolAddress((void**)&v,   g_v);
    cudaGetSymbolAddress((void**)&ctx, g_ctx);
    cudaGetSymbolAddress((void**)&t0,  g_t0);
    cudaGetSymbolAddress((void**)&y,   g_y);
    cudaGetSymbolAddress((void**)&mid, g_mid);
    cudaGetSymbolAddress((void**)&qp,  g_qp);
    cudaGetSymbolAddress((void**)&kp,  g_kp);

    cudaFuncSetAttribute(flash_kernel, cudaFuncAttributeMaxDynamicSharedMemorySize, FLASH_SMEM);

    embed_kernel<<<(NTOK*(DMODEL/4)+255)/256, 256>>>(x, emb_w, emb_b, pe, h);

    dim3 g512 (DMODEL/128, (NTOK+127)/128);   // (4, 63)
    dim3 g2048(DFFN/128,   (NTOK+127)/128);   // (16, 63)
    int lmN = NTOK*NHEAD*PDIM;

    for (int i = 0; i < NLAYER; i++){
        const float* Wqi = Wq + (size_t)i*DMODEL*DMODEL;  const float* bqi = bq + (size_t)i*DMODEL;
        const float* Wki = Wk + (size_t)i*DMODEL*DMODEL;  const float* bki = bk + (size_t)i*DMODEL;
        const float* Wvi = Wv + (size_t)i*DMODEL*DMODEL;  const float* bvi = bvv + (size_t)i*DMODEL;
        const float* Woi = Wo + (size_t)i*DMODEL*DMODEL;  const float* boi = bo + (size_t)i*DMODEL;
        const float* W1i = W1 + (size_t)i*DMODEL*DFFN;    const float* b1i = b1 + (size_t)i*DFFN;
        const float* W2i = W2 + (size_t)i*DFFN*DMODEL;    const float* b2i = b2 + (size_t)i*DMODEL;
        const float* g1i = g1 + (size_t)i*DMODEL;  const float* be1i = be1 + (size_t)i*DMODEL;
        const float* g2i = g2 + (size_t)i*DMODEL;  const float* be2i = be2 + (size_t)i*DMODEL;

        mma_gemm_kernel<0><<<g512, 128>>>(h, Wqi, bqi, nullptr, q, NTOK, DMODEL, DMODEL);
        mma_gemm_kernel<0><<<g512, 128>>>(h, Wki, bki, nullptr, k, NTOK, DMODEL, DMODEL);
        mma_gemm_kernel<0><<<g512, 128>>>(h, Wvi, bvi, nullptr, v, NTOK, DMODEL, DMODEL);

        lm_proj_kernel<<<(lmN+255)/256, 256>>>(q, lm_qw, lm_qb, qp);
        lm_proj_kernel<<<(lmN+255)/256, 256>>>(k, lm_kw, lm_kb, kp);

        flash_kernel<<<dim3((LL+63)/64, BB*NHEAD), 256, FLASH_SMEM>>>(q, k, v, qp, kp, ctx);

        mma_gemm_kernel<2><<<g512, 128>>>(ctx, Woi, boi, h, t0, NTOK, DMODEL, DMODEL);
        ln_kernel<<<NTOK, 128>>>(t0, nullptr, g1i, be1i, h);

        mma_gemm_kernel<1><<<g2048, 128>>>(h,   W1i, b1i, nullptr, mid, NTOK, DFFN,   DMODEL);
        mma_gemm_kernel<0><<<g512,  128>>>(mid, W2i, b2i, nullptr, y,   NTOK, DMODEL, DFFN);

        ln_kernel<<<NTOK, 128>>>(h,  y, g2i, be2i, t0);   // h2 = LN(h + y)
        ln_kernel<<<NTOK, 128>>>(t0, y, g2i, be2i, h);    // h  = LN(h2 + y)  (norm2 applied twice)
    }

    final_kernel<<<BB, DMODEL>>>(h, gn, bn, fc_w, fc_b, (float*)d_out);
}

// round 16
// speedup vs baseline: 2.8762x; 2.6538x over previous
#include <cuda_runtime.h>
#include <math.h>

#define BB      8
#define LL      1000
#define FFE     7
#define DMODEL  512
#define NHEAD   8
#define DK      64
#define PDIM    16
#define DFFN    2048
#define NLAYER  4
#define NPRED   50
#define NTOK    (BB*LL)
#define LN_EPS  1e-5f
#define ATT_SCALE 0.125f

// ---------------- scratch (device globals: no cudaMalloc allowed) ----------------
__device__ float g_h  [NTOK*DMODEL];
__device__ float g_q  [NTOK*DMODEL];
__device__ float g_k  [NTOK*DMODEL];
__device__ float g_v  [NTOK*DMODEL];
__device__ float g_ctx[NTOK*DMODEL];
__device__ float g_t0 [NTOK*DMODEL];
__device__ float g_y  [NTOK*DMODEL];
__device__ float g_mid[NTOK*DFFN];
__device__ float g_qp [NTOK*NHEAD*PDIM];
__device__ float g_kp [NTOK*NHEAD*PDIM];

__device__ __forceinline__ unsigned f2tf(float x){
    unsigned r;
    asm("cvt.rna.tf32.f32 %0, %1;" : "=r"(r) : "f"(x));
    return r;
}
__device__ __forceinline__ float htanh(float x){
    float r;
    asm("tanh.approx.f32 %0, %1;" : "=f"(r) : "f"(x));
    return r;
}
__device__ __forceinline__ void mma_tf32(float* c, const unsigned* a, const unsigned* b){
    asm volatile("mma.sync.aligned.m16n8k8.row.col.f32.tf32.tf32.f32 "
        "{%0,%1,%2,%3}, {%4,%5,%6,%7}, {%8,%9}, {%0,%1,%2,%3};"
        : "+f"(c[0]), "+f"(c[1]), "+f"(c[2]), "+f"(c[3])
        : "r"(a[0]), "r"(a[1]), "r"(a[2]), "r"(a[3]), "r"(b[0]), "r"(b[1]));
}

// ---------------- embedding: h = x@emb_w + emb_b + pe ----------------
__global__ void embed_kernel(const float* __restrict__ x, const float* __restrict__ ew,
                             const float* __restrict__ eb, const float* __restrict__ pe,
                             float* __restrict__ out)
{
    int idx = blockIdx.x*blockDim.x + threadIdx.x;
    if (idx >= NTOK*(DMODEL/4)) return;
    int d4  = idx & (DMODEL/4 - 1);
    int tok = idx >> 7;
    int lpos = tok % LL;
    int d = d4*4;
    float4 acc = *(const float4*)(eb + d);
    float4 pv  = *(const float4*)(pe + (size_t)lpos*DMODEL + d);
    acc.x += pv.x; acc.y += pv.y; acc.z += pv.z; acc.w += pv.w;
    #pragma unroll
    for (int f = 0; f < FFE; f++){
        float xv = x[tok*FFE + f];
        float4 wv = *(const float4*)(ew + (size_t)f*DMODEL + d);
        acc.x = fmaf(xv, wv.x, acc.x);
        acc.y = fmaf(xv, wv.y, acc.y);
        acc.z = fmaf(xv, wv.z, acc.z);
        acc.w = fmaf(xv, wv.w, acc.w);
    }
    *(float4*)(out + (size_t)tok*DMODEL + d) = acc;
}

// ---------------- TF32 tensor-core GEMM core (128 threads, tile 128x128, k32) ----
#define AS_STRIDE 36
#define BS_STRIDE 136

template<int EPI>
__device__ __forceinline__ void gemm_core(
    const float* __restrict__ A, const float* __restrict__ W,
    const float* __restrict__ bias, const float* __restrict__ res,
    float* __restrict__ C, int M, int N, int K, int m0, int n0,
    unsigned* As, unsigned* Bs)
{
    const int tid  = threadIdx.x;
    const int wid  = tid >> 5, lane = tid & 31;
    const int wm   = (wid & 1) * 64;
    const int wn   = (wid >> 1) * 64;
    const int gid  = lane >> 2, tig = lane & 3;

    float acc[4][8][4];
    #pragma unroll
    for (int mt = 0; mt < 4; mt++)
        #pragma unroll
        for (int nt = 0; nt < 8; nt++)
            #pragma unroll
            for (int j = 0; j < 4; j++) acc[mt][nt][j] = 0.f;

    for (int k0 = 0; k0 < K; k0 += 32){
        #pragma unroll
        for (int it = 0; it < 8; it++){
            int i  = it*128 + tid;
            int r  = i >> 3, c4 = (i & 7) * 4;
            float4 v = make_float4(0,0,0,0);
            int gm = m0 + r;
            if (gm < M) v = *(const float4*)(A + (size_t)gm*K + k0 + c4);
            *(uint4*)&As[r*AS_STRIDE + c4] =
                make_uint4(f2tf(v.x), f2tf(v.y), f2tf(v.z), f2tf(v.w));
        }
        #pragma unroll
        for (int it = 0; it < 8; it++){
            int i  = it*128 + tid;
            int kr = i >> 5, c4 = (i & 31) * 4;
            float4 v = *(const float4*)(W + (size_t)(k0+kr)*N + n0 + c4);
            *(uint4*)&Bs[kr*BS_STRIDE + c4] =
                make_uint4(f2tf(v.x), f2tf(v.y), f2tf(v.z), f2tf(v.w));
        }
        __syncthreads();

        #pragma unroll
        for (int k8 = 0; k8 < 4; k8++){
            unsigned afr[4][4], bfr[8][2];
            #pragma unroll
            for (int mt = 0; mt < 4; mt++){
                int r = wm + mt*16 + gid;
                const unsigned* p0 = &As[r*AS_STRIDE + k8*8];
                const unsigned* p1 = &As[(r+8)*AS_STRIDE + k8*8];
                afr[mt][0] = p0[tig];
                afr[mt][1] = p1[tig];
                afr[mt][2] = p0[tig+4];
                afr[mt][3] = p1[tig+4];
            }
            #pragma unroll
            for (int nt = 0; nt < 8; nt++){
                int n = wn + nt*8 + gid;
                bfr[nt][0] = Bs[(k8*8 + tig  )*BS_STRIDE + n];
                bfr[nt][1] = Bs[(k8*8 + tig+4)*BS_STRIDE + n];
            }
            #pragma unroll
            for (int mt = 0; mt < 4; mt++)
                #pragma unroll
                for (int nt = 0; nt < 8; nt++)
                    mma_tf32(acc[mt][nt], afr[mt], bfr[nt]);
        }
        __syncthreads();
    }

    #pragma unroll
    for (int mt = 0; mt < 4; mt++){
        #pragma unroll
        for (int half = 0; half < 2; half++){
            int gm = m0 + wm + mt*16 + gid + half*8;
            if (gm >= M) continue;
            float* crow = C + (size_t)gm*N;
            const float* rrow = (EPI == 2) ? (res + (size_t)gm*N) : nullptr;
            #pragma unroll
            for (int nt = 0; nt < 8; nt++){
                int gn = n0 + wn + nt*8 + tig*2;
                float v0 = acc[mt][nt][half*2+0] + bias[gn];
                float v1 = acc[mt][nt][half*2+1] + bias[gn+1];
                if (EPI == 1){ v0 = fmaxf(v0, 0.f); v1 = fmaxf(v1, 0.f); }
                if (EPI == 2){ v0 += rrow[gn]; v1 += rrow[gn+1]; }
                *(float2*)(crow + gn) = make_float2(v0, v1);
            }
        }
    }
}

template<int EPI>
__global__ __launch_bounds__(128, 2) void mma_gemm_kernel(
    const float* __restrict__ A, const float* __restrict__ W,
    const float* __restrict__ bias, const float* __restrict__ res,
    float* __restrict__ C, int M, int N, int K)
{
    __shared__ unsigned As[128*AS_STRIDE];
    __shared__ unsigned Bs[32*BS_STRIDE];
    gemm_core<EPI>(A, W, bias, res, C, M, N, K, blockIdx.y*128, blockIdx.x*128, As, Bs);
}

// fused QKV: grid.x = 12 (sel = x>>2 picks Q/K/V weight set, nb = x&3 picks n-block)
__global__ __launch_bounds__(128, 2) void qkv_gemm_kernel(
    const float* __restrict__ A,
    const float* __restrict__ Wq_, const float* __restrict__ bq_, float* __restrict__ qo,
    const float* __restrict__ Wk_, const float* __restrict__ bk_, float* __restrict__ ko,
    const float* __restrict__ Wv_, const float* __restrict__ bv_, float* __restrict__ vo,
    int M)
{
    __shared__ unsigned As[128*AS_STRIDE];
    __shared__ unsigned Bs[32*BS_STRIDE];
    int sel = blockIdx.x >> 2, nb = blockIdx.x & 3;
    const float* W  = (sel == 0) ? Wq_ : (sel == 1) ? Wk_ : Wv_;
    const float* bb = (sel == 0) ? bq_ : (sel == 1) ? bk_ : bv_;
    float*       C  = (sel == 0) ? qo  : (sel == 1) ? ko  : vo;
    gemm_core<0>(A, W, bb, nullptr, C, M, DMODEL, DMODEL, blockIdx.y*128, nb*128, As, Bs);
}

// ---------------- learned-mask projections (q and k fused via blockIdx.y) -------
__global__ void lm_proj2_kernel(const float* __restrict__ Xq, const float* __restrict__ Xk,
                                const float* __restrict__ Wmq, const float* __restrict__ bmq,
                                const float* __restrict__ Wmk, const float* __restrict__ bmk,
                                float* __restrict__ oq, float* __restrict__ ok)
{
    int t = blockIdx.x*blockDim.x + threadIdx.x;
    if (t >= NTOK*NHEAD*PDIM) return;
    const float* X  = blockIdx.y ? Xk  : Xq;
    const float* Wm = blockIdx.y ? Wmk : Wmq;
    const float* bm = blockIdx.y ? bmk : bmq;
    float* out      = blockIdx.y ? ok  : oq;
    int p   = t & (PDIM-1);
    int hh  = (t >> 4) & (NHEAD-1);
    int tok = t >> 7;
    const float* xr = X + (size_t)tok*DMODEL + hh*DK;
    float s = bm[p];
    #pragma unroll
    for (int d = 0; d < DK; d++) s = fmaf(xr[d], Wm[d*PDIM + p], s);
    out[t] = s;
}

// ---------------- flash attention, TF32 MMA --------------------------------------
// grid (16, B*H), 128 threads / 4 warps. Warp owns 16 q-rows. Ps aliases Ks.
#define FM_KS 68
#define FM_VS 72
#define FM_KP 20

__global__ __launch_bounds__(128, 2) void flash_mma_kernel(
    const float* __restrict__ Q, const float* __restrict__ Kg, const float* __restrict__ Vg,
    const float* __restrict__ QP, const float* __restrict__ KP, float* __restrict__ O)
{
    __shared__ unsigned Ks [64*FM_KS];   // K tile [s][d]; aliased as Ps [q][s] later
    __shared__ unsigned Vs [64*FM_VS];   // V tile [s][d]
    __shared__ unsigned KPs[64*FM_KP];   // KP tile [s][p]
    unsigned* Ps = Ks;

    const int tid  = threadIdx.x;
    const int wid  = tid >> 5, lane = tid & 31;
    const int gid  = lane >> 2, tig = lane & 3;
    const int wq   = wid * 16;
    const int q0   = blockIdx.x * 64;
    const int b    = blockIdx.y >> 3;
    const int h    = blockIdx.y & 7;

    // ---- preload Q / QP fragments (tf32, register-resident across all s-tiles)
    unsigned qa[8][4], qpa[2][4];
    {
        int r0 = q0 + wq + gid, r1 = r0 + 8;
        bool v0 = r0 < LL, v1 = r1 < LL;
        const float* Q0 = Q + ((size_t)(b*LL + (v0 ? r0 : 0))*NHEAD + h)*DK;
        const float* Q1 = Q + ((size_t)(b*LL + (v1 ? r1 : 0))*NHEAD + h)*DK;
        #pragma unroll
        for (int k8 = 0; k8 < 8; k8++){
            int c = k8*8 + tig;
            qa[k8][0] = f2tf(v0 ? Q0[c]   : 0.f);
            qa[k8][1] = f2tf(v1 ? Q1[c]   : 0.f);
            qa[k8][2] = f2tf(v0 ? Q0[c+4] : 0.f);
            qa[k8][3] = f2tf(v1 ? Q1[c+4] : 0.f);
        }
        const float* P0 = QP + ((size_t)(b*LL + (v0 ? r0 : 0))*NHEAD + h)*PDIM;
        const float* P1 = QP + ((size_t)(b*LL + (v1 ? r1 : 0))*NHEAD + h)*PDIM;
        #pragma unroll
        for (int k8 = 0; k8 < 2; k8++){
            int c = k8*8 + tig;
            qpa[k8][0] = f2tf(v0 ? P0[c]   : 0.f);
            qpa[k8][1] = f2tf(v1 ? P1[c]   : 0.f);
            qpa[k8][2] = f2tf(v0 ? P0[c+4] : 0.f);
            qpa[k8][3] = f2tf(v1 ? P1[c+4] : 0.f);
        }
    }

    float oacc[8][4];
    #pragma unroll
    for (int nt = 0; nt < 8; nt++)
        #pragma unroll
        for (int j = 0; j < 4; j++) oacc[nt][j] = 0.f;
    float m0 = -1e30f, m1 = -1e30f, l0 = 0.f, l1 = 0.f;

    for (int s0 = 0; s0 < LL; s0 += 64){
        __syncthreads();   // prev PV done reading Ps/Vs
        // ---- stage K, V tiles (tf32)
        #pragma unroll
        for (int it = 0; it < 8; it++){
            int i = it*128 + tid;
            int r = i >> 4, c4 = (i & 15)*4;
            int ls = s0 + r;
            float4 kv = make_float4(0,0,0,0), vv = kv;
            if (ls < LL){
                size_t base = ((size_t)(b*LL + ls)*NHEAD + h)*DK + c4;
                kv = *(const float4*)(Kg + base);
                vv = *(const float4*)(Vg + base);
            }
            *(uint4*)&Ks[r*FM_KS + c4] = make_uint4(f2tf(kv.x), f2tf(kv.y), f2tf(kv.z), f2tf(kv.w));
            *(uint4*)&Vs[r*FM_VS + c4] = make_uint4(f2tf(vv.x), f2tf(vv.y), f2tf(vv.z), f2tf(vv.w));
        }
        #pragma unroll
        for (int it = 0; it < 2; it++){
            int i = it*128 + tid;
            int r = i >> 2, c4 = (i & 3)*4;
            int ls = s0 + r;
            float4 kp = make_float4(0,0,0,0);
            if (ls < LL) kp = *(const float4*)(KP + ((size_t)(b*LL + ls)*NHEAD + h)*PDIM + c4);
            *(uint4*)&KPs[r*FM_KP + c4] = make_uint4(f2tf(kp.x), f2tf(kp.y), f2tf(kp.z), f2tf(kp.w));
        }
        __syncthreads();

        // ---- S = Q K^T (tensor) and M = QP KP^T (tensor)
        float sacc[8][4], macc[8][4];
        #pragma unroll
        for (int nt = 0; nt < 8; nt++)
            #pragma unroll
            for (int j = 0; j < 4; j++){ sacc[nt][j] = 0.f; macc[nt][j] = 0.f; }

        #pragma unroll
        for (int k8 = 0; k8 < 8; k8++)
            #pragma unroll
            for (int nt = 0; nt < 8; nt++){
                unsigned kb[2];
                kb[0] = Ks[(nt*8+gid)*FM_KS + k8*8 + tig];
                kb[1] = Ks[(nt*8+gid)*FM_KS + k8*8 + tig + 4];
                mma_tf32(sacc[nt], qa[k8], kb);
            }
        #pragma unroll
        for (int k8 = 0; k8 < 2; k8++)
            #pragma unroll
            for (int nt = 0; nt < 8; nt++){
                unsigned kb[2];
                kb[0] = KPs[(nt*8+gid)*FM_KP + k8*8 + tig];
                kb[1] = KPs[(nt*8+gid)*FM_KP + k8*8 + tig + 4];
                mma_tf32(macc[nt], qpa[k8], kb);
            }

        // ---- scores = S*scale + tanh(M), tail mask
        bool tail = (s0 + 64 > LL);
        #pragma unroll
        for (int nt = 0; nt < 8; nt++)
            #pragma unroll
            for (int j = 0; j < 4; j++){
                float v = fmaf(sacc[nt][j], ATT_SCALE, htanh(macc[nt][j]));
                if (tail && (s0 + nt*8 + tig*2 + (j & 1) >= LL)) v = -1e30f;
                sacc[nt][j] = v;
            }

        // ---- online softmax (two rows per thread: gid -> j0,1 ; gid+8 -> j2,3)
        float rmax0 = -1e30f, rmax1 = -1e30f;
        #pragma unroll
        for (int nt = 0; nt < 8; nt++){
            rmax0 = fmaxf(rmax0, fmaxf(sacc[nt][0], sacc[nt][1]));
            rmax1 = fmaxf(rmax1, fmaxf(sacc[nt][2], sacc[nt][3]));
        }
        rmax0 = fmaxf(rmax0, __shfl_xor_sync(0xffffffffu, rmax0, 1));
        rmax0 = fmaxf(rmax0, __shfl_xor_sync(0xffffffffu, rmax0, 2));
        rmax1 = fmaxf(rmax1, __shfl_xor_sync(0xffffffffu, rmax1, 1));
        rmax1 = fmaxf(rmax1, __shfl_xor_sync(0xffffffffu, rmax1, 2));
        float nm0 = fmaxf(m0, rmax0), nm1 = fmaxf(m1, rmax1);
        float a0 = __expf(m0 - nm0),  a1 = __expf(m1 - nm1);
        m0 = nm0; m1 = nm1;
        float rs0 = 0.f, rs1 = 0.f;
        #pragma unroll
        for (int nt = 0; nt < 8; nt++){
            float p0 = __expf(sacc[nt][0] - nm0);
            float p1 = __expf(sacc[nt][1] - nm0);
            float p2 = __expf(sacc[nt][2] - nm1);
            float p3 = __expf(sacc[nt][3] - nm1);
            rs0 += p0 + p1; rs1 += p2 + p3;
            sacc[nt][0] = p0; sacc[nt][1] = p1; sacc[nt][2] = p2; sacc[nt][3] = p3;
        }
        rs0 += __shfl_xor_sync(0xffffffffu, rs0, 1);
        rs0 += __shfl_xor_sync(0xffffffffu, rs0, 2);
        rs1 += __shfl_xor_sync(0xffffffffu, rs1, 1);
        rs1 += __shfl_xor_sync(0xffffffffu, rs1, 2);
        l0 = l0*a0 + rs0; l1 = l1*a1 + rs1;
        #pragma unroll
        for (int nt = 0; nt < 8; nt++){
            oacc[nt][0] *= a0; oacc[nt][1] *= a0;
            oacc[nt][2] *= a1; oacc[nt][3] *= a1;
        }

        __syncthreads();   // all warps done reading Ks (aliased with Ps)
        #pragma unroll
        for (int nt = 0; nt < 8; nt++){
            *(uint2*)&Ps[(wq+gid  )*FM_KS + nt*8 + tig*2] = make_uint2(f2tf(sacc[nt][0]), f2tf(sacc[nt][1]));
            *(uint2*)&Ps[(wq+gid+8)*FM_KS + nt*8 + tig*2] = make_uint2(f2tf(sacc[nt][2]), f2tf(sacc[nt][3]));
        }
        __syncthreads();

        // ---- O += P V (tensor)
        #pragma unroll
        for (int k8 = 0; k8 < 8; k8++){
            unsigned pa[4];
            pa[0] = Ps[(wq+gid  )*FM_KS + k8*8 + tig];
            pa[1] = Ps[(wq+gid+8)*FM_KS + k8*8 + tig];
            pa[2] = Ps[(wq+gid  )*FM_KS + k8*8 + tig + 4];
            pa[3] = Ps[(wq+gid+8)*FM_KS + k8*8 + tig + 4];
            #pragma unroll
            for (int nt = 0; nt < 8; nt++){
                unsigned vb[2];
                vb[0] = Vs[(k8*8+tig  )*FM_VS + nt*8 + gid];
                vb[1] = Vs[(k8*8+tig+4)*FM_VS + nt*8 + gid];
                mma_tf32(oacc[nt], pa, vb);
            }
        }
    }

    // ---- write O
    {
        int r0 = q0 + wq + gid, r1 = r0 + 8;
        float i0 = __fdividef(1.f, l0), i1 = __fdividef(1.f, l1);
        float* O0 = O + ((size_t)(b*LL + r0)*NHEAD + h)*DK;
        float* O1 = O + ((size_t)(b*LL + r1)*NHEAD + h)*DK;
        #pragma unroll
        for (int nt = 0; nt < 8; nt++){
            int col = nt*8 + tig*2;
            if (r0 < LL) *(float2*)(O0 + col) = make_float2(oacc[nt][0]*i0, oacc[nt][1]*i0);
            if (r1 < LL) *(float2*)(O1 + col) = make_float2(oacc[nt][2]*i1, oacc[nt][3]*i1);
        }
    }
}

// ---------------- layernorm: out = LN(A [+ Add]) * g + b ------------------------
__global__ void ln_kernel(const float* __restrict__ A, const float* __restrict__ Add,
                          const float* __restrict__ g, const float* __restrict__ bb,
                          float* __restrict__ out)
{
    int row = blockIdx.x;
    int tid = threadIdx.x;   // 128
    size_t off = (size_t)row*DMODEL + tid*4;
    float4 v = *(const float4*)(A + off);
    if (Add){
        float4 w = *(const float4*)(Add + off);
        v.x+=w.x; v.y+=w.y; v.z+=w.z; v.w+=w.w;
    }
    float s  = v.x+v.y+v.z+v.w;
    float s2 = v.x*v.x + v.y*v.y + v.z*v.z + v.w*v.w;
    #pragma unroll
    for (int o = 16; o > 0; o >>= 1){
        s  += __shfl_down_sync(0xffffffffu, s,  o);
        s2 += __shfl_down_sync(0xffffffffu, s2, o);
    }
    __shared__ float red[8];
    int wid = tid >> 5;
    if ((tid & 31) == 0){ red[wid] = s; red[wid+4] = s2; }
    __syncthreads();
    if (tid == 0){
        float ts  = red[0]+red[1]+red[2]+red[3];
        float ts2 = red[4]+red[5]+red[6]+red[7];
        float mean = ts * (1.f/DMODEL);
        float var  = ts2 * (1.f/DMODEL) - mean*mean;
        red[0] = mean; red[1] = rsqrtf(var + LN_EPS);
    }
    __syncthreads();
    float mean = red[0], rstd = red[1];
    float4 gv = *(const float4*)(g  + tid*4);
    float4 bv = *(const float4*)(bb + tid*4);
    float4 o;
    o.x = (v.x-mean)*rstd*gv.x + bv.x;
    o.y = (v.y-mean)*rstd*gv.y + bv.y;
    o.z = (v.z-mean)*rstd*gv.z + bv.z;
    o.w = (v.w-mean)*rstd*gv.w + bv.w;
    *(float4*)(out + off) = o;
}

// ---------------- fused double norm2: h = LN(LN(h+y)+y) --------------------------
__global__ void ln2x_kernel(const float* __restrict__ H, const float* __restrict__ Y,
                            const float* __restrict__ g, const float* __restrict__ bb,
                            float* __restrict__ out)
{
    int row = blockIdx.x;
    int tid = threadIdx.x;   // 128
    size_t off = (size_t)row*DMODEL + tid*4;
    float4 y = *(const float4*)(Y + off);
    float4 v = *(const float4*)(H + off);
    v.x+=y.x; v.y+=y.y; v.z+=y.z; v.w+=y.w;
    float4 gv = *(const float4*)(g  + tid*4);
    float4 bv = *(const float4*)(bb + tid*4);
    __shared__ float red[8];
    int wid = tid >> 5;

    #pragma unroll
    for (int pass = 0; pass < 2; pass++){
        float s  = v.x+v.y+v.z+v.w;
        float s2 = v.x*v.x + v.y*v.y + v.z*v.z + v.w*v.w;
        #pragma unroll
        for (int o = 16; o > 0; o >>= 1){
            s  += __shfl_down_sync(0xffffffffu, s,  o);
            s2 += __shfl_down_sync(0xffffffffu, s2, o);
        }
        if (pass) __syncthreads();
        if ((tid & 31) == 0){ red[wid] = s; red[wid+4] = s2; }
        __syncthreads();
        if (tid == 0){
            float ts  = red[0]+red[1]+red[2]+red[3];
            float ts2 = red[4]+red[5]+red[6]+red[7];
            float mean = ts * (1.f/DMODEL);
            float var  = ts2 * (1.f/DMODEL) - mean*mean;
            red[0] = mean; red[1] = rsqrtf(var + LN_EPS);
        }
        __syncthreads();
        float mean = red[0], rstd = red[1];
        v.x = (v.x-mean)*rstd*gv.x + bv.x;
        v.y = (v.y-mean)*rstd*gv.y + bv.y;
        v.z = (v.z-mean)*rstd*gv.z + bv.z;
        v.w = (v.w-mean)*rstd*gv.w + bv.w;
        if (pass == 0){ v.x+=y.x; v.y+=y.y; v.z+=y.z; v.w+=y.w; }
    }
    *(float4*)(out + off) = v;
}

// ---------------- final: LN(h[b, L-1, :]) @ fc_w + fc_b --------------------------
__global__ void final_kernel(const float* __restrict__ Hbuf, const float* __restrict__ gn,
    const float* __restrict__ bn, const float* __restrict__ fw, const float* __restrict__ fb,
    float* __restrict__ out)
{
    __shared__ float sh[DMODEL];
    __shared__ float red[34];
    int b = blockIdx.x, tid = threadIdx.x;  // 512
    float v = Hbuf[((size_t)(b*LL + LL-1))*DMODEL + tid];
    float s = v, s2 = v*v;
    #pragma unroll
    for (int o = 16; o > 0; o >>= 1){
        s  += __shfl_down_sync(0xffffffffu, s,  o);
        s2 += __shfl_down_sync(0xffffffffu, s2, o);
    }
    int wid = tid >> 5;
    if ((tid & 31) == 0){ red[wid] = s; red[wid+17] = s2; }
    __syncthreads();
    if (tid == 0){
        float ts = 0.f, ts2 = 0.f;
        #pragma unroll
        for (int i = 0; i < 16; i++){ ts += red[i]; ts2 += red[i+17]; }
        float mean = ts * (1.f/DMODEL);
        float var  = ts2 * (1.f/DMODEL) - mean*mean;
        red[16] = mean; red[33] = rsqrtf(var + LN_EPS);
    }
    __syncthreads();
    float mean = red[16], rstd = red[33];
    sh[tid] = (v - mean)*rstd*gn[tid] + bn[tid];
    __syncthreads();
    if (tid < NPRED){
        float acc = fb[tid];
        #pragma unroll 8
        for (int d = 0; d < DMODEL; d++) acc = fmaf(sh[d], fw[d*NPRED + tid], acc);
        out[b*NPRED + tid] = acc;
    }
}

// ---------------- host orchestration ---------------------------------------------
extern "C" void kernel_launch(void* const* d_in, const int* in_sizes, int n_in,
                              void* d_out, int out_size)
{
    const float* x     = (const float*)d_in[0];
    const float* emb_w = (const float*)d_in[1];
    const float* emb_b = (const float*)d_in[2];
    const float* pe    = (const float*)d_in[3];
    const float* Wq    = (const float*)d_in[4];
    const float* bq    = (const float*)d_in[5];
    const float* Wk    = (const float*)d_in[6];
    const float* bk    = (const float*)d_in[7];
    const float* Wv    = (const float*)d_in[8];
    const float* bvv   = (const float*)d_in[9];
    const float* Wo    = (const float*)d_in[10];
    const float* bo    = (const float*)d_in[11];
    const float* W1    = (const float*)d_in[12];
    const float* b1    = (const float*)d_in[13];
    const float* W2    = (const float*)d_in[14];
    const float* b2    = (const float*)d_in[15];
    const float* g1    = (const float*)d_in[16];
    const float* be1   = (const float*)d_in[17];
    const float* g2    = (const float*)d_in[18];
    const float* be2   = (const float*)d_in[19];
    const float* lm_qw = (const float*)d_in[20];
    const float* lm_qb = (const float*)d_in[21];
    const float* lm_kw = (const float*)d_in[22];
    const float* lm_kb = (const float*)d_in[23];
    const float* gn    = (const float*)d_in[24];
    const float* bn    = (const float*)d_in[25];
    const float* fc_w  = (const float*)d_in[26];
    const float* fc_b  = (const float*)d_in[27];

    float *h,*q,*k,*v,*ctx,*t0,*y,*mid,*qp,*kp;
    cudaGetSymbolAddress((void**)&h,   g_h);
    cudaGetSymbolAddress((void**)&q,   g_q);
    cudaGetSymbolAddress((void**)&k,   g_k);
    cudaGetSymbolAddress((void**)&v,   g_v);
    cudaGetSymbolAddress((void**)&ctx, g_ctx);
    cudaGetSymbolAddress((void**)&t0,  g_t0);
    cudaGetSymbolAddress((void**)&y,   g_y);
    cudaGetSymbolAddress((void**)&mid, g_mid);
    cudaGetSymbolAddress((void**)&qp,  g_qp);
    cudaGetSymbolAddress((void**)&kp,  g_kp);

    embed_kernel<<<(NTOK*(DMODEL/4)+255)/256, 256>>>(x, emb_w, emb_b, pe, h);

    dim3 gqkv(12, (NTOK+127)/128);            // (12, 63)
    dim3 g512 (DMODEL/128, (NTOK+127)/128);   // (4, 63)
    dim3 g2048(DFFN/128,   (NTOK+127)/128);   // (16, 63)
    int lmN = NTOK*NHEAD*PDIM;

    for (int i = 0; i < NLAYER; i++){
        const float* Wqi = Wq + (size_t)i*DMODEL*DMODEL;  const float* bqi = bq + (size_t)i*DMODEL;
        const float* Wki = Wk + (size_t)i*DMODEL*DMODEL;  const float* bki = bk + (size_t)i*DMODEL;
        const float* Wvi = Wv + (size_t)i*DMODEL*DMODEL;  const float* bvi = bvv + (size_t)i*DMODEL;
        const float* Woi = Wo + (size_t)i*DMODEL*DMODEL;  const float* boi = bo + (size_t)i*DMODEL;
        const float* W1i = W1 + (size_t)i*DMODEL*DFFN;    const float* b1i = b1 + (size_t)i*DFFN;
        const float* W2i = W2 + (size_t)i*DFFN*DMODEL;    const float* b2i = b2 + (size_t)i*DMODEL;
        const float* g1i = g1 + (size_t)i*DMODEL;  const float* be1i = be1 + (size_t)i*DMODEL;
        const float* g2i = g2 + (size_t)i*DMODEL;  const float* be2i = be2 + (size_t)i*DMODEL;

        qkv_gemm_kernel<<<gqkv, 128>>>(h, Wqi, bqi, q, Wki, bki, k, Wvi, bvi, v, NTOK);

        lm_proj2_kernel<<<dim3((lmN+255)/256, 2), 256>>>(q, k, lm_qw, lm_qb, lm_kw, lm_kb, qp, kp);

        flash_mma_kernel<<<dim3((LL+63)/64, BB*NHEAD), 128>>>(q, k, v, qp, kp, ctx);

        mma_gemm_kernel<2><<<g512, 128>>>(ctx, Woi, boi, h, t0, NTOK, DMODEL, DMODEL);
        ln_kernel<<<NTOK, 128>>>(t0, nullptr, g1i, be1i, h);

        mma_gemm_kernel<1><<<g2048, 128>>>(h,   W1i, b1i, nullptr, mid, NTOK, DFFN,   DMODEL);
        mma_gemm_kernel<0><<<g512,  128>>>(mid, W2i, b2i, nullptr, y,   NTOK, DMODEL, DFFN);

        ln2x_kernel<<<NTOK, 128>>>(h, y, g2i, be2i, h);   // h = LN(LN(h+y)+y)
    }

    final_kernel<<<BB, DMODEL>>>(h, gn, bn, fc_w, fc_b, (float*)d_out);
}